// round 15
// baseline (speedup 1.0000x reference)
#include <cuda_runtime.h>
#include <cuda_fp16.h>
#include <cstdint>
#include <cstddef>

// ---------------- problem constants ----------------
static constexpr int Bm = 1024;     // batch rows
static constexpr int Dk = 512;      // feature dim (K)
static constexpr int Cn = 100000;   // classes (N)
static constexpr float S_s = 30.0f;
static constexpr float M_m = 0.4f;

// GEMM config
#define BMT 128
#define BNT 128
#define BKT 32
static constexpr int NCHUNK = Dk / BKT;   // 16
static constexpr int STAGES = 4;
static constexpr int A_STAGE = BMT * BKT * 2;   // 8192 B
static constexpr int B_STAGE = BKT * BNT * 2;   // 8192 B
static constexpr int SMEM_BYTES = STAGES * (A_STAGE + B_STAGE);  // 65536

// ---------------- device scratch (no runtime allocation allowed) ----------------
__device__ __half g_Xh[Bm * Dk];                      // normalized x, fp16
__device__ float  g_Xn[Bm * Dk];                      // normalized x, fp32 (loss tgt)
__device__ __half g_Wh[(size_t)Dk * (size_t)Cn];      // W converted to fp16
__device__ float g_winv[Cn];                          // 1 / ||W[:,c]||
__device__ float g_rowsum[Bm];                        // sum_c exp(S*cos)
__device__ float g_lsum;                              // loss partial-sum accumulator
__device__ int   g_ldone;                             // loss block ticket counter
__device__ float g_cos_scratch[(size_t)Bm * (size_t)Cn]; // fallback cossim store

// ---------------- helpers ----------------
__device__ __forceinline__ uint32_t f2h2(float a, float b) {
    __half2 h = __floats2half2_rn(a, b);
    return *reinterpret_cast<uint32_t*>(&h);
}

__device__ __forceinline__ void mma16(float* d, const uint32_t* a, const uint32_t* b) {
    asm volatile(
        "mma.sync.aligned.m16n8k16.row.col.f32.f16.f16.f32 "
        "{%0,%1,%2,%3}, {%4,%5,%6,%7}, {%8,%9}, {%0,%1,%2,%3};\n"
        : "+f"(d[0]), "+f"(d[1]), "+f"(d[2]), "+f"(d[3])
        : "r"(a[0]), "r"(a[1]), "r"(a[2]), "r"(a[3]), "r"(b[0]), "r"(b[1]));
}
__device__ __forceinline__ void ldsm4(uint32_t* r, uint32_t addr) {
    asm volatile("ldmatrix.sync.aligned.m8n8.x4.shared.b16 {%0,%1,%2,%3}, [%4];"
                 : "=r"(r[0]), "=r"(r[1]), "=r"(r[2]), "=r"(r[3]) : "r"(addr));
}
__device__ __forceinline__ void ldsm4t(uint32_t* r, uint32_t addr) {
    asm volatile("ldmatrix.sync.aligned.m8n8.x4.trans.shared.b16 {%0,%1,%2,%3}, [%4];"
                 : "=r"(r[0]), "=r"(r[1]), "=r"(r[2]), "=r"(r[3]) : "r"(addr));
}
__device__ __forceinline__ void cp16(uint32_t smem_dst, const void* gsrc) {
    asm volatile("cp.async.cg.shared.global [%0], [%1], 16;"
                 :: "r"(smem_dst), "l"(gsrc) : "memory");
}
__device__ __forceinline__ void cp_commit() {
    asm volatile("cp.async.commit_group;" ::: "memory");
}
template <int N>
__device__ __forceinline__ void cp_wait() {
    asm volatile("cp.async.wait_group %0;" :: "n"(N) : "memory");
}

// swizzled byte offsets inside the smem tiles (16B cell granularity)
// A tile: 128 rows x 32 halfs (64B/row = 4 cells): cell ^= (row>>1)&3
__device__ __forceinline__ int a_byte(int r, int c) {
    return r * 64 + ((c ^ ((r >> 1) & 3)) << 4);
}
// B tile: 32 k-rows x 128 halfs (256B/row = 16 cells): cell ^= k&7
__device__ __forceinline__ int b_byte(int k, int c) {
    return k * 256 + ((c ^ (k & 7)) << 4);
}

// ---------------- kernel 1: L2-normalize rows of x -> fp16 + fp32; zero accumulators --
__global__ void normalize_x_kernel(const float* __restrict__ x) {
    const int b = blockIdx.x;           // 1024 blocks
    const int t = threadIdx.x;          // 128 threads
    float4 v = reinterpret_cast<const float4*>(x + (size_t)b * Dk)[t];
    float ss = v.x * v.x + v.y * v.y + v.z * v.z + v.w * v.w;
    #pragma unroll
    for (int o = 16; o > 0; o >>= 1) ss += __shfl_xor_sync(0xffffffffu, ss, o);
    __shared__ float ws[4];
    if ((t & 31) == 0) ws[t >> 5] = ss;
    __syncthreads();
    const float tot = ws[0] + ws[1] + ws[2] + ws[3];
    const float inv = 1.0f / fmaxf(sqrtf(tot), 1e-12f);
    float4 f;
    f.x = v.x * inv; f.y = v.y * inv; f.z = v.z * inv; f.w = v.w * inv;
    uint2 st;
    st.x = f2h2(f.x, f.y);
    st.y = f2h2(f.z, f.w);
    reinterpret_cast<uint2*>(g_Xh + (size_t)b * Dk)[t] = st;
    reinterpret_cast<float4*>(g_Xn + (size_t)b * Dk)[t] = f;
    if (t == 0) g_rowsum[b] = 0.0f;
    if (b == 0 && t == 0) { g_lsum = 0.0f; g_ldone = 0; }
}

// ---------------- kernel 2: W column inv-norms + fp16 conversion (one pass) -------
__global__ void wprep_kernel(const float* __restrict__ Wp) {
    const int c0 = (blockIdx.x * blockDim.x + threadIdx.x) * 4;   // 4 columns/thread
    if (c0 >= Cn) return;
    float s0 = 0.0f, s1 = 0.0f, s2 = 0.0f, s3 = 0.0f;
    #pragma unroll 4
    for (int d = 0; d < Dk; ++d) {
        const float4 w = *reinterpret_cast<const float4*>(Wp + (size_t)d * Cn + c0);
        s0 = fmaf(w.x, w.x, s0);
        s1 = fmaf(w.y, w.y, s1);
        s2 = fmaf(w.z, w.z, s2);
        s3 = fmaf(w.w, w.w, s3);
        uint2 h;
        h.x = f2h2(w.x, w.y);
        h.y = f2h2(w.z, w.w);
        *reinterpret_cast<uint2*>(g_Wh + (size_t)d * Cn + c0) = h;
    }
    float4 o;
    o.x = 1.0f / fmaxf(sqrtf(s0), 1e-12f);
    o.y = 1.0f / fmaxf(sqrtf(s1), 1e-12f);
    o.z = 1.0f / fmaxf(sqrtf(s2), 1e-12f);
    o.w = 1.0f / fmaxf(sqrtf(s3), 1e-12f);
    *reinterpret_cast<float4*>(g_winv + c0) = o;
}

// ---------------- kernel 3: fp16 GEMM, cp.async 4-stage + fused epilogue ----------
__global__ void __launch_bounds__(256, 2)
gemm_cos_kernel(float* __restrict__ outp) {
    extern __shared__ __align__(128) uint8_t smem[];
    uint8_t* As = smem;                       // STAGES x 8KB
    uint8_t* Bs = smem + STAGES * A_STAGE;    // STAGES x 8KB

    float* __restrict__ outc = outp ? outp : g_cos_scratch;

    const int tid  = threadIdx.x;
    const int lane = tid & 31;
    const int g    = lane >> 2;
    const int t    = lane & 3;
    const int warp = tid >> 5;
    const int wm   = warp & 1;    // 2 warps in M (64 rows each)
    const int wn   = warp >> 1;   // 4 warps in N (32 cols each)
    const int bN   = blockIdx.y * BNT;
    const int bM   = blockIdx.x * BMT;

    const uint32_t sA0 = (uint32_t)__cvta_generic_to_shared(As);
    const uint32_t sB0 = (uint32_t)__cvta_generic_to_shared(Bs);

    // ---- load coordinates (cp.async, 16B granules) ----
    const int arow = tid >> 1;
    const int ac0  = (tid & 1) * 2;
    const int bk   = tid >> 3;
    const int bc0  = (tid & 7) * 2;
    const int bn0  = bN + bc0 * 8;
    const bool bvalid = (bn0 + 16 <= Cn);   // Cn % 16 == 0 -> all-or-nothing

    const __half* Abase = g_Xh + (size_t)(bM + arow) * Dk + ac0 * 8;

    auto issue_stage = [&](int s) {
        const int buf = s % STAGES;
        const int kc  = s * BKT;
        const uint32_t dA = sA0 + buf * A_STAGE;
        const uint32_t dB = sB0 + buf * B_STAGE;
        cp16(dA + a_byte(arow, ac0),     Abase + kc);
        cp16(dA + a_byte(arow, ac0 + 1), Abase + kc + 8);
        if (bvalid) {
            const __half* Bp = g_Wh + (size_t)(kc + bk) * Cn + bn0;
            cp16(dB + b_byte(bk, bc0),     Bp);
            cp16(dB + b_byte(bk, bc0 + 1), Bp + 8);
        } else {
            const uint4 z = make_uint4(0, 0, 0, 0);
            *reinterpret_cast<uint4*>(Bs + buf * B_STAGE + b_byte(bk, bc0))     = z;
            *reinterpret_cast<uint4*>(Bs + buf * B_STAGE + b_byte(bk, bc0 + 1)) = z;
        }
    };

    float acc[4][4][4];
    #pragma unroll
    for (int i = 0; i < 4; ++i)
        #pragma unroll
        for (int j = 0; j < 4; ++j)
            #pragma unroll
            for (int k = 0; k < 4; ++k) acc[i][j][k] = 0.0f;

    // per-lane ldmatrix address components
    const int rl = lane & 15;     // row within 16-row tile
    const int cp = lane >> 4;     // cell selector (second half of lanes)

    auto compute_chunk = [&](int buf) {
        const uint32_t sAb = sA0 + buf * A_STAGE;
        const uint32_t sBb = sB0 + buf * B_STAGE;
        #pragma unroll
        for (int ks = 0; ks < 2; ++ks) {
            uint32_t af[4][4];
            uint32_t bf[4][2];
            #pragma unroll
            for (int mt = 0; mt < 4; ++mt)
                ldsm4(af[mt], sAb + a_byte(wm * 64 + mt * 16 + rl, ks * 2 + cp));
            // x4.trans: lanes 0-15 -> n-cell (wn*4+2j), lanes 16-31 -> (wn*4+2j+1)
            #pragma unroll
            for (int j = 0; j < 2; ++j)
                ldsm4t(&bf[2 * j][0], sBb + b_byte(ks * 16 + rl, wn * 4 + 2 * j + cp));
            #pragma unroll
            for (int mt = 0; mt < 4; ++mt)
                #pragma unroll
                for (int nt = 0; nt < 4; ++nt)
                    mma16(acc[mt][nt], af[mt], bf[nt]);
        }
    };

    // ---- 4-stage pipelined mainloop (fully unrolled: compile-time stage indices) ----
    issue_stage(0); cp_commit();
    issue_stage(1); cp_commit();
    issue_stage(2); cp_commit();

    #pragma unroll
    for (int it = 0; it < NCHUNK; ++it) {
        cp_wait<2>();
        __syncthreads();
        if (it + 3 < NCHUNK) issue_stage(it + 3);
        cp_commit();                 // empty groups at tail keep wait-depth math valid
        compute_chunk(it % STAGES);
    }

    // -------- fused epilogue: scale by 1/||w_c||, clip, store, accumulate exp-sums ----
    float rsum[4][2];
    #pragma unroll
    for (int mt = 0; mt < 4; ++mt) { rsum[mt][0] = 0.0f; rsum[mt][1] = 0.0f; }

    #pragma unroll
    for (int mt = 0; mt < 4; ++mt) {
        const int gr0 = bM + wm * 64 + mt * 16 + g;
        #pragma unroll
        for (int nt = 0; nt < 4; ++nt) {
            const int gc = bN + wn * 32 + nt * 8 + t * 2;
            if (gc < Cn) {
                const float iw0 = g_winv[gc];
                const float iw1 = g_winv[gc + 1];
                float c0 = fminf(fmaxf(acc[mt][nt][0] * iw0, -1.0f), 1.0f);
                float c1 = fminf(fmaxf(acc[mt][nt][1] * iw1, -1.0f), 1.0f);
                float c2 = fminf(fmaxf(acc[mt][nt][2] * iw0, -1.0f), 1.0f);
                float c3 = fminf(fmaxf(acc[mt][nt][3] * iw1, -1.0f), 1.0f);
                *reinterpret_cast<float2*>(&outc[(size_t)gr0 * Cn + gc]) = make_float2(c0, c1);
                *reinterpret_cast<float2*>(&outc[(size_t)(gr0 + 8) * Cn + gc]) = make_float2(c2, c3);
                rsum[mt][0] += __expf(S_s * c0) + __expf(S_s * c1);
                rsum[mt][1] += __expf(S_s * c2) + __expf(S_s * c3);
            }
        }
    }
    #pragma unroll
    for (int mt = 0; mt < 4; ++mt) {
        #pragma unroll
        for (int h = 0; h < 2; ++h) {
            float v = rsum[mt][h];
            v += __shfl_xor_sync(0xffffffffu, v, 1);
            v += __shfl_xor_sync(0xffffffffu, v, 2);
            if (t == 0) {
                const int gr = bM + wm * 64 + mt * 16 + g + h * 8;
                atomicAdd(&g_rowsum[gr], v);
            }
        }
    }
}

// ---------------- kernel 4: parallel loss with fp32 tgt recompute ----------------
// tgt is recomputed in fp32 (dot of fp32-normalized row with raw W column, scaled
// by winv) to remove the S*dtgt fp16 amplification from the loss scalar. The
// exp(S*tgt) subtracted from rowsum uses the same fp32 tgt; the residual mismatch
// vs the fp16 term inside rowsum is ~1e-7 relative to excl.
__global__ void loss_kernel(const float* __restrict__ Wp,
                            const int* __restrict__ lbl32,
                            float* __restrict__ loss_out) {
    const int b = blockIdx.x * 64 + threadIdx.x;   // grid 16 x 64 threads

    // detect label dtype within this block's slice (int64 labels -> high words all 0)
    __shared__ int nz;
    if (threadIdx.x == 0) nz = 0;
    __syncthreads();
    if (lbl32[2 * b + 1] != 0) atomicOr(&nz, 1);
    __syncthreads();

    int label;
    if (nz == 0) label = (int)(reinterpret_cast<const long long*>(lbl32)[b]);
    else         label = lbl32[b];

    // fp32 dot: Xn[b,:] . W[:,label]
    const float* xr = g_Xn + (size_t)b * Dk;
    float dot = 0.0f;
    #pragma unroll 8
    for (int d = 0; d < Dk; ++d)
        dot = fmaf(xr[d], __ldg(Wp + (size_t)d * Cn + label), dot);
    const float tgt = fminf(fmaxf(dot * g_winv[label], -1.0f), 1.0f);

    const float excl = g_rowsum[b] - __expf(S_s * tgt);
    const float num  = S_s * (tgt - M_m);
    const float L    = num - logf(expf(num) + excl);

    float v = L;
    #pragma unroll
    for (int o = 16; o > 0; o >>= 1) v += __shfl_xor_sync(0xffffffffu, v, o);
    __shared__ float red[2];
    if ((threadIdx.x & 31) == 0) red[threadIdx.x >> 5] = v;
    __syncthreads();
    if (threadIdx.x == 0) {
        const float s = red[0] + red[1];
        atomicAdd(&g_lsum, s);
        __threadfence();
        const int tkt = atomicAdd(&g_ldone, 1);
        if (tkt == (int)gridDim.x - 1) {
            const float total = atomicAdd(&g_lsum, 0.0f);   // ordered read after all adds
            loss_out[0] = -(total / (float)Bm);
        }
    }
}

// ---------------- launch ----------------
extern "C" void kernel_launch(void* const* d_in, const int* in_sizes, int n_in,
                              void* d_out, int out_size) {
    const float* x   = (const float*)d_in[0];
    const float* W   = (const float*)d_in[1];
    const int*   lbl = (const int*)d_in[2];
    float* out = (float*)d_out;

    const long long BC = (long long)Bm * (long long)Cn;   // 102,400,000
    const bool cos_in_out = ((long long)out_size >= BC);

    static bool attr_set = false;
    if (!attr_set) {
        cudaFuncSetAttribute(gemm_cos_kernel,
                             cudaFuncAttributeMaxDynamicSharedMemorySize, SMEM_BYTES);
        attr_set = true;
    }

    normalize_x_kernel<<<Bm, 128>>>(x);
    wprep_kernel<<<(Cn / 4 + 255) / 256, 256>>>(W);

    // grid: x = M-blocks (8, fast-moving), y = N-blocks (782) -> W tiles L2-shared
    dim3 gg(Bm / BMT, (Cn + BNT - 1) / BNT);   // (8, 782)
    gemm_cos_kernel<<<gg, 256, SMEM_BYTES>>>(cos_in_out ? out : nullptr);

    if (cos_in_out && (long long)out_size >= BC + 1) {
        loss_kernel<<<16, 64>>>(W, lbl, out + BC);
    } else if (!cos_in_out && out_size >= 1) {
        loss_kernel<<<16, 64>>>(W, lbl, out);
    }
}